// round 15
// baseline (speedup 1.0000x reference)
#include <cuda_runtime.h>

#define NT 256

// ---------------- static smem layout (floats), total 12224 <= 12288 (48KB) ----------------
// Stage A: P1 0..7488 | WIN 7488..9528 | C1 9528..11576 | W1S 11576..12152 | B1S 12152..12160
// Stage B: P1 0..7488 | C2 7488..10048 | P2 10048..11968 | SCR 11968..12224
// Stage C: W3S 0..6272 (stride 196) | C3 6272..8832 | F 8832..9088 | RED 9088..9200 | P2 alive
#define P1_OFF   0
#define WIN_OFF  7488
#define C1_OFF   9528
#define W1S_OFF  11576
#define B1S_OFF  12152
#define C2_OFF   7488
#define P2_OFF   10048
#define W3_OFF   0
#define C3_OFF   6272
#define F_OFF    8832
#define RED_OFF  9088
#define SCR_OFF  11968
#define SMEM_FLOATS 12224

// padded conv2 weights [16 co][8 ci][12], filled idempotently by every CTA
__device__ float w2pad_g[16 * 8 * 12];

static __device__ __forceinline__ float lrelu(float v) { return v > 0.0f ? v : 0.01f * v; }

// fetch 4 consecutive floats (even float2-aligned base) as two float2
static __device__ __forceinline__ void ld4(float* dst, const float* p) {
    float2 a = *reinterpret_cast<const float2*>(p);
    float2 b = *reinterpret_cast<const float2*>(p + 2);
    dst[0] = a.x; dst[1] = a.y; dst[2] = b.x; dst[3] = b.y;
}

// load 9 floats from a 16B-aligned 12-stride row: 2x LDS.128 + 1 scalar
static __device__ __forceinline__ void ld9a(float* w, const float* row) {
    float4 a = *reinterpret_cast<const float4*>(row);
    float4 b = *reinterpret_cast<const float4*>(row + 4);
    w[0]=a.x; w[1]=a.y; w[2]=a.z; w[3]=a.w;
    w[4]=b.x; w[5]=b.y; w[6]=b.z; w[7]=b.w;
    w[8]=row[8];
}

// ---- stage A chunk: conv1 (2 copairs/warp + x-pair + row-half), pool1 (co-quad) ----
template<int CH>   // P1 rows produced (4 or 2)
__device__ __forceinline__ void stageA_chunk(const float* __restrict__ xg,
                                             const float* __restrict__ wp1,
                                             const float* __restrict__ bp1,
                                             float* sm, int tid, int r0)
{
    constexpr int WROWS = 2 * CH + 2;
    float* WIN = sm + WIN_OFF;                 // [6][WROWS][34]
    float* C1  = sm + C1_OFF;                  // [8][2*CH][32]
    float* P1  = sm + P1_OFF;                  // [8][52][18]

    // load input window (zero-padded)
    for (int g = tid; g < 6 * WROWS * 34; g += NT) {
        int c   = g / (WROWS * 34);
        int rem = g - c * (WROWS * 34);
        int r   = rem / 34;
        int wx  = rem - r * 34;
        int iy  = 2 * r0 + r - 1;
        int ix  = wx - 1;
        float v = 0.0f;
        if (iy >= 0 && iy < 100 && (unsigned)ix < 32u)
            v = xg[c * 3200 + iy * 32 + ix];
        WIN[c * (WROWS * 34) + r * 34 + wx] = v;
    }
    __syncthreads();

    // conv1: 128 thr; warp = (cogrp 2) x (rh 2); lane = (copair-in-grp 2) x (xpair 16)
    if (tid < 128) {
        const int w      = tid >> 5;
        const int rh     = w & 1;
        const int cogrp  = w >> 1;
        const int lane   = tid & 31;
        const int copair = cogrp * 2 + (lane >> 4);
        const int xp     = lane & 15;
        const int co0 = copair * 2, co1 = co0 + 1;
        const int x0  = 2 * xp;
        const int y0  = rh * CH;
        float acc0[2][CH], acc1[2][CH];
        const float b0 = sm[B1S_OFF + co0], b1v = sm[B1S_OFF + co1];
#pragma unroll
        for (int r = 0; r < CH; r++) {
            acc0[0][r] = b0; acc0[1][r] = b0;
            acc1[0][r] = b1v; acc1[1][r] = b1v;
        }
#pragma unroll
        for (int ci = 0; ci < 6; ci++) {
            float wA[9], wB[9];
            ld9a(wA, sm + W1S_OFF + co0 * 72 + ci * 12);
            ld9a(wB, sm + W1S_OFF + co1 * 72 + ci * 12);
            const float* p = WIN + ci * (WROWS * 34) + y0 * 34 + x0;
            float vr[3][4];
#pragma unroll
            for (int q = 0; q < 2; q++) ld4(vr[q], p + q * 34);
#pragma unroll
            for (int r = 2; r < CH + 2; r++) {
                ld4(vr[r % 3], p + r * 34);
                const int rr = r - 2;
                float a00 = acc0[0][rr], a01 = acc0[1][rr];
                float a10 = acc1[0][rr], a11 = acc1[1][rr];
#pragma unroll
                for (int ky = 0; ky < 3; ky++) {
                    const int sl = (rr + ky) % 3;
#pragma unroll
                    for (int k = 0; k < 3; k++) {
                        a00 = fmaf(vr[sl][k],     wA[ky*3+k], a00);
                        a01 = fmaf(vr[sl][k + 1], wA[ky*3+k], a01);
                        a10 = fmaf(vr[sl][k],     wB[ky*3+k], a10);
                        a11 = fmaf(vr[sl][k + 1], wB[ky*3+k], a11);
                    }
                }
                acc0[0][rr] = a00; acc0[1][rr] = a01;
                acc1[0][rr] = a10; acc1[1][rr] = a11;
            }
        }
#pragma unroll
        for (int r = 0; r < CH; r++) {
            float2 s0 = make_float2(lrelu(acc0[0][r]), lrelu(acc0[1][r]));
            float2 s1 = make_float2(lrelu(acc1[0][r]), lrelu(acc1[1][r]));
            *reinterpret_cast<float2*>(C1 + co0 * (2*CH*32) + (y0 + r) * 32 + x0) = s0;
            *reinterpret_cast<float2*>(C1 + co1 * (2*CH*32) + (y0 + r) * 32 + x0) = s1;
        }
    }
    __syncthreads();

    // pool1: co-quad: (cq in 2: 4 co) x (i in CH) x (j in 16); inputs shared across 4 co
    if (tid < 2 * CH * 16) {
        const int cq  = tid / (CH * 16);
        const int rem = tid - cq * (CH * 16);
        const int i = rem >> 4, j = rem & 15;
        const int cb = cq * 4;
        float a[4];
#pragma unroll
        for (int c = 0; c < 4; c++) a[c] = __ldg(bp1 + cb + c);
#pragma unroll
        for (int m = 0; m < 8; m++) {
            const float* p = C1 + m * (2*CH*32) + (2*i) * 32 + 2*j;
            float2 v0 = *reinterpret_cast<const float2*>(p);
            float2 v1 = *reinterpret_cast<const float2*>(p + 32);
#pragma unroll
            for (int c = 0; c < 4; c++) {
                float4 wv = __ldg(reinterpret_cast<const float4*>(wp1 + (cb + c) * 32) + m);
                a[c] = fmaf(v0.x, wv.x, fmaf(v0.y, wv.y, fmaf(v1.x, wv.z, fmaf(v1.y, wv.w, a[c]))));
            }
        }
#pragma unroll
        for (int c = 0; c < 4; c++)
            P1[(cb + c) * 936 + (r0 + i + 1) * 18 + (j + 1)] = a[c];
    }
    // no trailing sync between chunks: next WIN load is disjoint; caller syncs before C1 reuse
}

__global__ void __launch_bounds__(NT, 4)
enc_kernel(const float* __restrict__ x,
           const float* __restrict__ w1,  const float* __restrict__ b1,
           const float* __restrict__ w2,  const float* __restrict__ b2,
           const float* __restrict__ w3,  const float* __restrict__ b3,
           const float* __restrict__ wp1, const float* __restrict__ bp1,
           const float* __restrict__ wp2, const float* __restrict__ bp2,
           const float* __restrict__ wp3, const float* __restrict__ bp3,
           const float* __restrict__ wmu, const float* __restrict__ bmu,
           const float* __restrict__ wlv, const float* __restrict__ blv,
           float* __restrict__ out)
{
    __shared__ float sm[SMEM_FLOATS];
    const int tid = threadIdx.x;
    const int bi  = blockIdx.x;
    const float* xg = x + (size_t)bi * 19200;

    for (int i = tid; i < 7488; i += NT) sm[P1_OFF + i] = 0.0f;   // zero padded P1
    // stage conv1 weights padded [8][6][12] + bias into smem
    for (int g = tid; g < 432; g += NT) {
        int co = g / 54, rem = g - co * 54;
        int ci = rem / 9,  k  = rem - ci * 9;
        sm[W1S_OFF + co * 72 + ci * 12 + k] = __ldg(w1 + g);
    }
    if (tid < 8) sm[B1S_OFF + tid] = __ldg(b1 + tid);
    // fill padded conv2 weights in global scratch (idempotent across CTAs)
    for (int g = tid; g < 1152; g += NT) {
        int co = g / 72, rem = g - co * 72;
        int ci = rem / 9,  k  = rem - ci * 9;
        w2pad_g[co * 96 + ci * 12 + k] = __ldg(w2 + g);
    }
    __syncthreads();

    // ---- stage A: 12 chunks of 4 P1-rows + 1 of 2 ----
#pragma unroll 1
    for (int c = 0; c < 12; c++)
        stageA_chunk<4>(xg, wp1, bp1, sm, tid, c * 4);
    stageA_chunk<2>(xg, wp1, bp1, sm, tid, 48);

    // barrier before reusing C1/W1S space (C2/P2 overlap them)
    __syncthreads();

    for (int i = tid; i < 1920; i += NT) sm[P2_OFF + i] = 0.0f;   // zero padded P2
    __syncthreads();

    // ---- stage B: conv2 (co-pair + x-pair + row-half) + pool2 (m-split) ----
#pragma unroll 1
    for (int t = 0; t < 5; t++) {
        float* P1 = sm + P1_OFF;
        float* C2 = sm + C2_OFF;   // [16][10][16]
        float* P2 = sm + P2_OFF;   // [16][12][10]
        if (tid < 128) {   // conv2: (copair 8) x (xpair 8) x (rh 2); 5 rows each
            const int copair = tid >> 4;
            const int l4     = tid & 15;
            const int xp     = l4 >> 1;
            const int rh     = l4 & 1;
            const int co0 = copair * 2, co1 = co0 + 1;
            const int x0  = 2 * xp;
            const int y0  = rh * 5;
            float acc0[2][5], acc1[2][5];
            const float b0 = __ldg(b2 + co0), b1v = __ldg(b2 + co1);
#pragma unroll
            for (int r = 0; r < 5; r++) {
                acc0[0][r] = b0; acc0[1][r] = b0;
                acc1[0][r] = b1v; acc1[1][r] = b1v;
            }
#pragma unroll
            for (int ci = 0; ci < 8; ci++) {
                float wA[9], wB[9];
                ld9a(wA, w2pad_g + co0 * 96 + ci * 12);
                ld9a(wB, w2pad_g + co1 * 96 + ci * 12);
                const float* p = P1 + ci * 936 + (10 * t + y0) * 18 + x0;
                float vr[3][4];
#pragma unroll
                for (int q = 0; q < 2; q++) ld4(vr[q], p + q * 18);
#pragma unroll
                for (int r = 2; r < 7; r++) {
                    ld4(vr[r % 3], p + r * 18);
                    const int rr = r - 2;
                    float a00 = acc0[0][rr], a01 = acc0[1][rr];
                    float a10 = acc1[0][rr], a11 = acc1[1][rr];
#pragma unroll
                    for (int ky = 0; ky < 3; ky++) {
                        const int sl = (rr + ky) % 3;
#pragma unroll
                        for (int k = 0; k < 3; k++) {
                            a00 = fmaf(vr[sl][k],     wA[ky*3+k], a00);
                            a01 = fmaf(vr[sl][k + 1], wA[ky*3+k], a01);
                            a10 = fmaf(vr[sl][k],     wB[ky*3+k], a10);
                            a11 = fmaf(vr[sl][k + 1], wB[ky*3+k], a11);
                        }
                    }
                    acc0[0][rr] = a00; acc0[1][rr] = a01;
                    acc1[0][rr] = a10; acc1[1][rr] = a11;
                }
            }
#pragma unroll
            for (int r = 0; r < 5; r++) {
                float2 s0 = make_float2(lrelu(acc0[0][r]), lrelu(acc0[1][r]));
                float2 s1 = make_float2(lrelu(acc1[0][r]), lrelu(acc1[1][r]));
                *reinterpret_cast<float2*>(C2 + co0 * 160 + (y0 + r) * 16 + x0) = s0;
                *reinterpret_cast<float2*>(C2 + co1 * 160 + (y0 + r) * 16 + x0) = s1;
            }
        }
        __syncthreads();
        {   // pool2: 256 thr = (mh 2) x (co 16) x (j 8); both i rows per thread
            const int mh = tid >> 7;
            const int co = (tid >> 3) & 15;
            const int j  = tid & 7;
            float a0 = 0.0f, a1 = 0.0f;
            const float2* wq = reinterpret_cast<const float2*>(wp2 + co * 160 + mh * 80);
            const float* pb  = C2 + mh * 8 * 160 + 2 * j;
#pragma unroll
            for (int mm = 0; mm < 8; mm++) {
                const float* prow = pb + mm * 160;
#pragma unroll
                for (int dy = 0; dy < 5; dy++) {
                    float2 ww = __ldg(wq + mm * 5 + dy);
                    float2 v0 = *reinterpret_cast<const float2*>(prow + dy * 16);
                    float2 v1 = *reinterpret_cast<const float2*>(prow + 80 + dy * 16);
                    a0 = fmaf(v0.x, ww.x, fmaf(v0.y, ww.y, a0));
                    a1 = fmaf(v1.x, ww.x, fmaf(v1.y, ww.y, a1));
                }
            }
            float* scr = sm + SCR_OFF;
            if (mh) { scr[co * 16 + j] = a0; scr[co * 16 + 8 + j] = a1; }
            __syncthreads();
            if (!mh) {
                const float b = __ldg(bp2 + co);
                a0 += b + scr[co * 16 + j];
                a1 += b + scr[co * 16 + 8 + j];
                P2[co * 120 + (2 * t + 1) * 10 + (j + 1)] = a0;
                P2[co * 120 + (2 * t + 2) * 10 + (j + 1)] = a1;
            }
        }
        __syncthreads();
    }

    // ---- stage C: stage w3 padded [32 co x 196][16 ci x 12] (conflict-free float4) ----
    for (int g = tid; g < 4608; g += NT) {
        int co = g / 144, rem = g - co * 144;
        int ci = rem / 9,  k  = rem - ci * 9;
        sm[W3_OFF + co * 196 + ci * 12 + k] = __ldg(w3 + g);
    }
    __syncthreads();

    if (tid < 128) {   // conv3: (copair 16) x (xpair 4) x (rh 2); 5 rows; float4 weights
        float* P2 = sm + P2_OFF;
        float* C3 = sm + C3_OFF;   // [32][10][8]
        const int copair = tid >> 3;
        const int l3     = tid & 7;
        const int xp     = l3 >> 1;
        const int rh     = l3 & 1;
        const int co0 = copair * 2, co1 = co0 + 1;
        const int x0  = 2 * xp;
        const int y0  = rh * 5;
        float acc0[2][5], acc1[2][5];
        const float b0 = __ldg(b3 + co0), b1v = __ldg(b3 + co1);
#pragma unroll
        for (int r = 0; r < 5; r++) {
            acc0[0][r] = b0; acc0[1][r] = b0;
            acc1[0][r] = b1v; acc1[1][r] = b1v;
        }
#pragma unroll
        for (int ci = 0; ci < 16; ci++) {
            float wA[9], wB[9];
            ld9a(wA, sm + W3_OFF + co0 * 196 + ci * 12);
            ld9a(wB, sm + W3_OFF + co1 * 196 + ci * 12);
            const float* p = P2 + ci * 120 + y0 * 10 + x0;
            float vr[3][4];
#pragma unroll
            for (int q = 0; q < 2; q++) ld4(vr[q], p + q * 10);
#pragma unroll
            for (int r = 2; r < 7; r++) {
                ld4(vr[r % 3], p + r * 10);
                const int rr = r - 2;
                float a00 = acc0[0][rr], a01 = acc0[1][rr];
                float a10 = acc1[0][rr], a11 = acc1[1][rr];
#pragma unroll
                for (int ky = 0; ky < 3; ky++) {
                    const int sl = (rr + ky) % 3;
#pragma unroll
                    for (int k = 0; k < 3; k++) {
                        a00 = fmaf(vr[sl][k],     wA[ky*3+k], a00);
                        a01 = fmaf(vr[sl][k + 1], wA[ky*3+k], a01);
                        a10 = fmaf(vr[sl][k],     wB[ky*3+k], a10);
                        a11 = fmaf(vr[sl][k + 1], wB[ky*3+k], a11);
                    }
                }
                acc0[0][rr] = a00; acc0[1][rr] = a01;
                acc1[0][rr] = a10; acc1[1][rr] = a11;
            }
        }
#pragma unroll
        for (int r = 0; r < 5; r++) {
            float2 s0 = make_float2(lrelu(acc0[0][r]), lrelu(acc0[1][r]));
            float2 s1 = make_float2(lrelu(acc1[0][r]), lrelu(acc1[1][r]));
            *reinterpret_cast<float2*>(C3 + co0 * 80 + (y0 + r) * 8 + x0) = s0;
            *reinterpret_cast<float2*>(C3 + co1 * 80 + (y0 + r) * 8 + x0) = s1;
        }
    }
    __syncthreads();

    {   // pool3: co-quad: 64 thr = (mh 2) x (cq 8: 4 co) x (j 4); inputs shared
        float* C3  = sm + C3_OFF;
        float* scr = sm + SCR_OFF;
        const int mh = tid >> 5;
        const int cq = (tid >> 2) & 7;
        const int j  = tid & 3;
        const int cb = cq * 4;
        float a[4][2];
        if (tid < 64) {
#pragma unroll
            for (int c = 0; c < 4; c++) { a[c][0] = 0.0f; a[c][1] = 0.0f; }
            const float* pb = C3 + mh * 16 * 80 + 2 * j;
#pragma unroll
            for (int mm = 0; mm < 16; mm++) {
                const float* prow = pb + mm * 80;
#pragma unroll
                for (int dy = 0; dy < 5; dy++) {
                    float2 v0 = *reinterpret_cast<const float2*>(prow + dy * 8);
                    float2 v1 = *reinterpret_cast<const float2*>(prow + 40 + dy * 8);
#pragma unroll
                    for (int c = 0; c < 4; c++) {
                        float2 ww = __ldg(reinterpret_cast<const float2*>(
                            wp3 + (cb + c) * 320 + mh * 160) + mm * 5 + dy);
                        a[c][0] = fmaf(v0.x, ww.x, fmaf(v0.y, ww.y, a[c][0]));
                        a[c][1] = fmaf(v1.x, ww.x, fmaf(v1.y, ww.y, a[c][1]));
                    }
                }
            }
            if (mh) {
#pragma unroll
                for (int c = 0; c < 4; c++) {
                    scr[(cb + c) * 8 + j]     = a[c][0];
                    scr[(cb + c) * 8 + 4 + j] = a[c][1];
                }
            }
        }
        __syncthreads();
        if (tid < 64 && mh == 0) {
#pragma unroll
            for (int c = 0; c < 4; c++) {
                const float b = __ldg(bp3 + cb + c);
                sm[F_OFF + (cb + c) * 8 + j]     = a[c][0] + b + scr[(cb + c) * 8 + j];
                sm[F_OFF + (cb + c) * 8 + 4 + j] = a[c][1] + b + scr[(cb + c) * 8 + 4 + j];
            }
        }
    }
    __syncthreads();

    // ---- heads ----
    {
        const float fv = sm[F_OFF + tid];
        float part[14];
#pragma unroll
        for (int o = 0; o < 7; o++) part[o]     = fv * __ldg(wmu + o * 256 + tid);
#pragma unroll
        for (int o = 0; o < 7; o++) part[7 + o] = fv * __ldg(wlv + o * 256 + tid);
#pragma unroll
        for (int off = 16; off > 0; off >>= 1) {
#pragma unroll
            for (int o = 0; o < 14; o++)
                part[o] += __shfl_down_sync(0xffffffffu, part[o], off);
        }
        float* red = sm + RED_OFF;
        if ((tid & 31) == 0) {
            int wp = tid >> 5;
#pragma unroll
            for (int o = 0; o < 14; o++) red[wp * 14 + o] = part[o];
        }
        __syncthreads();
        if (tid < 14) {
            float s = 0.0f;
#pragma unroll
            for (int wp = 0; wp < 8; wp++) s += red[wp * 14 + tid];
            if (tid < 7) {
                out[(size_t)bi * 7 + tid] = s + __ldg(bmu + tid);
            } else {
                int q = tid - 7;
                float v = s + __ldg(blv + q);
                v = fminf(fmaxf(v, -5.0f), 0.0f);
                out[(size_t)gridDim.x * 7 + (size_t)bi * 7 + q] = v;
            }
        }
    }
}

extern "C" void kernel_launch(void* const* d_in, const int* in_sizes, int n_in,
                              void* d_out, int out_size)
{
    // ---- unit detection: w1 is uniquely 432 elements == 1728 bytes ----
    int div = 1;
    {
        bool saw432 = false, saw1728 = false;
        for (int i = 0; i < n_in; i++) {
            if (in_sizes[i] == 432)  saw432 = true;
            if (in_sizes[i] == 1728) saw1728 = true;
        }
        if (!saw432 && saw1728) div = 4;
    }

    // ---- size-based input dispatch ----
    const float* p[17] = {0};
    int c8 = 0, c16 = 0, c32 = 0, c1792 = 0, c7 = 0;
    long xsz = 0;
    for (int i = 0; i < n_in; i++) {
        const float* q = (const float*)d_in[i];
        const int sz = in_sizes[i] / div;
        switch (sz) {
            case 432:   p[1]  = q; break;                      // w1
            case 1152:  p[3]  = q; break;                      // w2
            case 4608:  p[5]  = q; break;                      // w3
            case 256:   p[7]  = q; break;                      // wp1
            case 2560:  p[9]  = q; break;                      // wp2
            case 10240: p[11] = q; break;                      // wp3
            case 8:    p[c8++   ? 8  : 2]  = q; break;         // b1 then bp1
            case 16:   p[c16++  ? 10 : 4]  = q; break;         // b2 then bp2
            case 32:   p[c32++  ? 12 : 6]  = q; break;         // b3 then bp3
            case 1792: p[c1792++? 15 : 13] = q; break;         // wmu then wlv
            case 7:    p[c7++   ? 16 : 14] = q; break;         // bmu then blv
            default:
                if (sz > xsz) { p[0] = q; xsz = sz; }
                break;
        }
    }
    float* out = (float*)d_out;
    int B = (int)(xsz / (6 * 100 * 32));
    if (B < 1) B = 1;

    enc_kernel<<<B, NT>>>(
        p[0], p[1], p[2], p[3], p[4], p[5], p[6], p[7], p[8], p[9], p[10],
        p[11], p[12], p[13], p[14], p[15], p[16], out);
    (void)out_size;
}

// round 16
// speedup vs baseline: 1.2637x; 1.2637x over previous
#include <cuda_runtime.h>

#define NT 256

// ---------------- static smem layout (floats), total 12224 <= 12288 (48KB) ----------------
// Stage A: P1 0..7488 | WIN 7488..9528 | C1 9528..11576 | W1S 11576..12152 | B1S 12152..12160
// Stage B: P1 0..7488 | C2 7488..10048 | P2 10048..11968 | SCR 11968..12224
// Stage C: W3S 0..6272 (stride 196) | C3 6272..8832 | F 8832..9088 | RED 9088..9200 | P2 alive
#define P1_OFF   0
#define WIN_OFF  7488
#define C1_OFF   9528
#define W1S_OFF  11576
#define B1S_OFF  12152
#define C2_OFF   7488
#define P2_OFF   10048
#define W3_OFF   0
#define C3_OFF   6272
#define F_OFF    8832
#define RED_OFF  9088
#define SCR_OFF  11968
#define SMEM_FLOATS 12224

static __device__ __forceinline__ float lrelu(float v) { return v > 0.0f ? v : 0.01f * v; }

// load 9 floats from a 4B-aligned global offset using at most 1 scalar + 4 float2 LDG
static __device__ __forceinline__ void load9(float* w, const float* base, int off) {
    if (off & 1) {
        w[0] = __ldg(base + off);
        const float2* q = reinterpret_cast<const float2*>(base + off + 1);
#pragma unroll
        for (int k = 0; k < 4; k++) { float2 t = __ldg(q + k); w[1 + 2*k] = t.x; w[2 + 2*k] = t.y; }
    } else {
        const float2* q = reinterpret_cast<const float2*>(base + off);
#pragma unroll
        for (int k = 0; k < 4; k++) { float2 t = __ldg(q + k); w[2*k] = t.x; w[2*k + 1] = t.y; }
        w[8] = __ldg(base + off + 8);
    }
}

// fetch 4 consecutive floats (even float2-aligned base) as two float2
static __device__ __forceinline__ void ld4(float* dst, const float* p) {
    float2 a = *reinterpret_cast<const float2*>(p);
    float2 b = *reinterpret_cast<const float2*>(p + 2);
    dst[0] = a.x; dst[1] = a.y; dst[2] = b.x; dst[3] = b.y;
}

// load 9 floats from a 16B-aligned 12-stride smem row: 2x LDS.128 + 1 scalar
static __device__ __forceinline__ void ld9a(float* w, const float* row) {
    float4 a = *reinterpret_cast<const float4*>(row);
    float4 b = *reinterpret_cast<const float4*>(row + 4);
    w[0]=a.x; w[1]=a.y; w[2]=a.z; w[3]=a.w;
    w[4]=b.x; w[5]=b.y; w[6]=b.z; w[7]=b.w;
    w[8]=row[8];
}

// ---- stage A chunk: conv1 (2 copairs/warp + x-pair + row-half, smem weights),
//      pool1 (co-pair, R14 layout) ----
template<int CH>   // P1 rows produced (4 or 2)
__device__ __forceinline__ void stageA_chunk(const float* __restrict__ xg,
                                             const float* __restrict__ wp1,
                                             const float* __restrict__ bp1,
                                             float* sm, int tid, int r0)
{
    constexpr int WROWS = 2 * CH + 2;
    float* WIN = sm + WIN_OFF;                 // [6][WROWS][34]
    float* C1  = sm + C1_OFF;                  // [8][2*CH][32]
    float* P1  = sm + P1_OFF;                  // [8][52][18]

    // load input window (zero-padded)
    for (int g = tid; g < 6 * WROWS * 34; g += NT) {
        int c   = g / (WROWS * 34);
        int rem = g - c * (WROWS * 34);
        int r   = rem / 34;
        int wx  = rem - r * 34;
        int iy  = 2 * r0 + r - 1;
        int ix  = wx - 1;
        float v = 0.0f;
        if (iy >= 0 && iy < 100 && (unsigned)ix < 32u)
            v = xg[c * 3200 + iy * 32 + ix];
        WIN[c * (WROWS * 34) + r * 34 + wx] = v;
    }
    __syncthreads();

    // conv1: 128 thr; warp = (cogrp 2) x (rh 2); lane = (copair-in-grp 2) x (xpair 16)
    if (tid < 128) {
        const int w      = tid >> 5;
        const int rh     = w & 1;
        const int cogrp  = w >> 1;
        const int lane   = tid & 31;
        const int copair = cogrp * 2 + (lane >> 4);
        const int xp     = lane & 15;
        const int co0 = copair * 2, co1 = co0 + 1;
        const int x0  = 2 * xp;
        const int y0  = rh * CH;
        float acc0[2][CH], acc1[2][CH];
        const float b0 = sm[B1S_OFF + co0], b1v = sm[B1S_OFF + co1];
#pragma unroll
        for (int r = 0; r < CH; r++) {
            acc0[0][r] = b0; acc0[1][r] = b0;
            acc1[0][r] = b1v; acc1[1][r] = b1v;
        }
#pragma unroll
        for (int ci = 0; ci < 6; ci++) {
            float wA[9], wB[9];
            ld9a(wA, sm + W1S_OFF + co0 * 72 + ci * 12);
            ld9a(wB, sm + W1S_OFF + co1 * 72 + ci * 12);
            const float* p = WIN + ci * (WROWS * 34) + y0 * 34 + x0;
            float vr[3][4];
#pragma unroll
            for (int q = 0; q < 2; q++) ld4(vr[q], p + q * 34);
#pragma unroll
            for (int r = 2; r < CH + 2; r++) {
                ld4(vr[r % 3], p + r * 34);
                const int rr = r - 2;
                float a00 = acc0[0][rr], a01 = acc0[1][rr];
                float a10 = acc1[0][rr], a11 = acc1[1][rr];
#pragma unroll
                for (int ky = 0; ky < 3; ky++) {
                    const int sl = (rr + ky) % 3;
#pragma unroll
                    for (int k = 0; k < 3; k++) {
                        a00 = fmaf(vr[sl][k],     wA[ky*3+k], a00);
                        a01 = fmaf(vr[sl][k + 1], wA[ky*3+k], a01);
                        a10 = fmaf(vr[sl][k],     wB[ky*3+k], a10);
                        a11 = fmaf(vr[sl][k + 1], wB[ky*3+k], a11);
                    }
                }
                acc0[0][rr] = a00; acc0[1][rr] = a01;
                acc1[0][rr] = a10; acc1[1][rr] = a11;
            }
        }
#pragma unroll
        for (int r = 0; r < CH; r++) {
            float2 s0 = make_float2(lrelu(acc0[0][r]), lrelu(acc0[1][r]));
            float2 s1 = make_float2(lrelu(acc1[0][r]), lrelu(acc1[1][r]));
            *reinterpret_cast<float2*>(C1 + co0 * (2*CH*32) + (y0 + r) * 32 + x0) = s0;
            *reinterpret_cast<float2*>(C1 + co1 * (2*CH*32) + (y0 + r) * 32 + x0) = s1;
        }
    }
    __syncthreads();

    // pool1 (R14): (co-pair in 4) x (i in CH) x (j in 16)
    if (tid < 4 * CH * 16) {
        const int copair = tid / (CH * 16);
        const int rem    = tid - copair * (CH * 16);
        const int i = rem >> 4, j = rem & 15;
        const int co0 = copair * 2, co1 = co0 + 1;
        float a0 = __ldg(bp1 + co0), a1 = __ldg(bp1 + co1);
        const float4* wq0 = reinterpret_cast<const float4*>(wp1 + co0 * 32);
        const float4* wq1 = reinterpret_cast<const float4*>(wp1 + co1 * 32);
#pragma unroll
        for (int m = 0; m < 8; m++) {
            const float* p = C1 + m * (2*CH*32) + (2*i) * 32 + 2*j;
            float2 v0 = *reinterpret_cast<const float2*>(p);
            float2 v1 = *reinterpret_cast<const float2*>(p + 32);
            float4 w0 = __ldg(wq0 + m), w1v = __ldg(wq1 + m);
            a0 = fmaf(v0.x, w0.x, fmaf(v0.y, w0.y, fmaf(v1.x, w0.z, fmaf(v1.y, w0.w, a0))));
            a1 = fmaf(v0.x, w1v.x, fmaf(v0.y, w1v.y, fmaf(v1.x, w1v.z, fmaf(v1.y, w1v.w, a1))));
        }
        P1[co0 * 936 + (r0 + i + 1) * 18 + (j + 1)] = a0;
        P1[co1 * 936 + (r0 + i + 1) * 18 + (j + 1)] = a1;
    }
    // no trailing sync between chunks: next WIN load is disjoint; caller syncs before C1 reuse
}

__global__ void __launch_bounds__(NT, 4)
enc_kernel(const float* __restrict__ x,
           const float* __restrict__ w1,  const float* __restrict__ b1,
           const float* __restrict__ w2,  const float* __restrict__ b2,
           const float* __restrict__ w3,  const float* __restrict__ b3,
           const float* __restrict__ wp1, const float* __restrict__ bp1,
           const float* __restrict__ wp2, const float* __restrict__ bp2,
           const float* __restrict__ wp3, const float* __restrict__ bp3,
           const float* __restrict__ wmu, const float* __restrict__ bmu,
           const float* __restrict__ wlv, const float* __restrict__ blv,
           float* __restrict__ out)
{
    __shared__ float sm[SMEM_FLOATS];
    const int tid = threadIdx.x;
    const int bi  = blockIdx.x;
    const float* xg = x + (size_t)bi * 19200;

    for (int i = tid; i < 7488; i += NT) sm[P1_OFF + i] = 0.0f;   // zero padded P1
    // stage conv1 weights padded [8][6][12] + bias into smem (once per image)
    for (int g = tid; g < 432; g += NT) {
        int co = g / 54, rem = g - co * 54;
        int ci = rem / 9,  k  = rem - ci * 9;
        sm[W1S_OFF + co * 72 + ci * 12 + k] = __ldg(w1 + g);
    }
    if (tid < 8) sm[B1S_OFF + tid] = __ldg(b1 + tid);
    __syncthreads();

    // ---- stage A: 12 chunks of 4 P1-rows + 1 of 2 ----
#pragma unroll 1
    for (int c = 0; c < 12; c++)
        stageA_chunk<4>(xg, wp1, bp1, sm, tid, c * 4);
    stageA_chunk<2>(xg, wp1, bp1, sm, tid, 48);

    // barrier before reusing C1/W1S space (C2/P2 overlap them) — R8 race fix
    __syncthreads();

    for (int i = tid; i < 1920; i += NT) sm[P2_OFF + i] = 0.0f;   // zero padded P2
    __syncthreads();

    // ---- stage B: conv2 (co-pair + x-pair + row-half, LDG weights) + pool2 (m-split) ----
#pragma unroll 1
    for (int t = 0; t < 5; t++) {
        float* P1 = sm + P1_OFF;
        float* C2 = sm + C2_OFF;   // [16][10][16]
        float* P2 = sm + P2_OFF;   // [16][12][10]
        if (tid < 128) {   // conv2: (copair 8) x (xpair 8) x (rh 2); 5 rows each
            const int copair = tid >> 4;
            const int l4     = tid & 15;
            const int xp     = l4 >> 1;
            const int rh     = l4 & 1;
            const int co0 = copair * 2, co1 = co0 + 1;
            const int x0  = 2 * xp;
            const int y0  = rh * 5;
            float acc0[2][5], acc1[2][5];
            const float b0 = __ldg(b2 + co0), b1v = __ldg(b2 + co1);
#pragma unroll
            for (int r = 0; r < 5; r++) {
                acc0[0][r] = b0; acc0[1][r] = b0;
                acc1[0][r] = b1v; acc1[1][r] = b1v;
            }
#pragma unroll
            for (int ci = 0; ci < 8; ci++) {
                float wA[9], wB[9];
                load9(wA, w2, co0 * 72 + ci * 9);
                load9(wB, w2, co1 * 72 + ci * 9);
                const float* p = P1 + ci * 936 + (10 * t + y0) * 18 + x0;
                float vr[3][4];
#pragma unroll
                for (int q = 0; q < 2; q++) ld4(vr[q], p + q * 18);
#pragma unroll
                for (int r = 2; r < 7; r++) {
                    ld4(vr[r % 3], p + r * 18);
                    const int rr = r - 2;
                    float a00 = acc0[0][rr], a01 = acc0[1][rr];
                    float a10 = acc1[0][rr], a11 = acc1[1][rr];
#pragma unroll
                    for (int ky = 0; ky < 3; ky++) {
                        const int sl = (rr + ky) % 3;
#pragma unroll
                        for (int k = 0; k < 3; k++) {
                            a00 = fmaf(vr[sl][k],     wA[ky*3+k], a00);
                            a01 = fmaf(vr[sl][k + 1], wA[ky*3+k], a01);
                            a10 = fmaf(vr[sl][k],     wB[ky*3+k], a10);
                            a11 = fmaf(vr[sl][k + 1], wB[ky*3+k], a11);
                        }
                    }
                    acc0[0][rr] = a00; acc0[1][rr] = a01;
                    acc1[0][rr] = a10; acc1[1][rr] = a11;
                }
            }
#pragma unroll
            for (int r = 0; r < 5; r++) {
                float2 s0 = make_float2(lrelu(acc0[0][r]), lrelu(acc0[1][r]));
                float2 s1 = make_float2(lrelu(acc1[0][r]), lrelu(acc1[1][r]));
                *reinterpret_cast<float2*>(C2 + co0 * 160 + (y0 + r) * 16 + x0) = s0;
                *reinterpret_cast<float2*>(C2 + co1 * 160 + (y0 + r) * 16 + x0) = s1;
            }
        }
        __syncthreads();
        {   // pool2 (R14): 256 thr = (mh 2) x (co 16) x (j 8); both i rows per thread
            const int mh = tid >> 7;
            const int co = (tid >> 3) & 15;
            const int j  = tid & 7;
            float a0 = 0.0f, a1 = 0.0f;
            const float2* wq = reinterpret_cast<const float2*>(wp2 + co * 160 + mh * 80);
            const float* pb  = C2 + mh * 8 * 160 + 2 * j;
#pragma unroll
            for (int mm = 0; mm < 8; mm++) {
                const float* prow = pb + mm * 160;
#pragma unroll
                for (int dy = 0; dy < 5; dy++) {
                    float2 ww = __ldg(wq + mm * 5 + dy);
                    float2 v0 = *reinterpret_cast<const float2*>(prow + dy * 16);
                    float2 v1 = *reinterpret_cast<const float2*>(prow + 80 + dy * 16);
                    a0 = fmaf(v0.x, ww.x, fmaf(v0.y, ww.y, a0));
                    a1 = fmaf(v1.x, ww.x, fmaf(v1.y, ww.y, a1));
                }
            }
            float* scr = sm + SCR_OFF;
            if (mh) { scr[co * 16 + j] = a0; scr[co * 16 + 8 + j] = a1; }
            __syncthreads();
            if (!mh) {
                const float b = __ldg(bp2 + co);
                a0 += b + scr[co * 16 + j];
                a1 += b + scr[co * 16 + 8 + j];
                P2[co * 120 + (2 * t + 1) * 10 + (j + 1)] = a0;
                P2[co * 120 + (2 * t + 2) * 10 + (j + 1)] = a1;
            }
        }
        __syncthreads();
    }

    // ---- stage C: stage w3 padded [32 co x 196][16 ci x 12] (float4-loadable) ----
    for (int g = tid; g < 4608; g += NT) {
        int co = g / 144, rem = g - co * 144;
        int ci = rem / 9,  k  = rem - ci * 9;
        sm[W3_OFF + co * 196 + ci * 12 + k] = __ldg(w3 + g);
    }
    __syncthreads();

    if (tid < 128) {   // conv3: (copair 16) x (xpair 4) x (rh 2); 5 rows; float4 weights
        float* P2 = sm + P2_OFF;
        float* C3 = sm + C3_OFF;   // [32][10][8]
        const int copair = tid >> 3;
        const int l3     = tid & 7;
        const int xp     = l3 >> 1;
        const int rh     = l3 & 1;
        const int co0 = copair * 2, co1 = co0 + 1;
        const int x0  = 2 * xp;
        const int y0  = rh * 5;
        float acc0[2][5], acc1[2][5];
        const float b0 = __ldg(b3 + co0), b1v = __ldg(b3 + co1);
#pragma unroll
        for (int r = 0; r < 5; r++) {
            acc0[0][r] = b0; acc0[1][r] = b0;
            acc1[0][r] = b1v; acc1[1][r] = b1v;
        }
#pragma unroll
        for (int ci = 0; ci < 16; ci++) {
            float wA[9], wB[9];
            ld9a(wA, sm + W3_OFF + co0 * 196 + ci * 12);
            ld9a(wB, sm + W3_OFF + co1 * 196 + ci * 12);
            const float* p = P2 + ci * 120 + y0 * 10 + x0;
            float vr[3][4];
#pragma unroll
            for (int q = 0; q < 2; q++) ld4(vr[q], p + q * 10);
#pragma unroll
            for (int r = 2; r < 7; r++) {
                ld4(vr[r % 3], p + r * 10);
                const int rr = r - 2;
                float a00 = acc0[0][rr], a01 = acc0[1][rr];
                float a10 = acc1[0][rr], a11 = acc1[1][rr];
#pragma unroll
                for (int ky = 0; ky < 3; ky++) {
                    const int sl = (rr + ky) % 3;
#pragma unroll
                    for (int k = 0; k < 3; k++) {
                        a00 = fmaf(vr[sl][k],     wA[ky*3+k], a00);
                        a01 = fmaf(vr[sl][k + 1], wA[ky*3+k], a01);
                        a10 = fmaf(vr[sl][k],     wB[ky*3+k], a10);
                        a11 = fmaf(vr[sl][k + 1], wB[ky*3+k], a11);
                    }
                }
                acc0[0][rr] = a00; acc0[1][rr] = a01;
                acc1[0][rr] = a10; acc1[1][rr] = a11;
            }
        }
#pragma unroll
        for (int r = 0; r < 5; r++) {
            float2 s0 = make_float2(lrelu(acc0[0][r]), lrelu(acc0[1][r]));
            float2 s1 = make_float2(lrelu(acc1[0][r]), lrelu(acc1[1][r]));
            *reinterpret_cast<float2*>(C3 + co0 * 80 + (y0 + r) * 8 + x0) = s0;
            *reinterpret_cast<float2*>(C3 + co1 * 80 + (y0 + r) * 8 + x0) = s1;
        }
    }
    __syncthreads();

    {   // pool3 (R14): 256 thr = (mh 2) x (co 32) x (j 4); both i rows per thread
        float* C3 = sm + C3_OFF;
        const int mh = tid >> 7;
        const int co = (tid >> 2) & 31;
        const int j  = tid & 3;
        float a0 = 0.0f, a1 = 0.0f;
        const float2* wq = reinterpret_cast<const float2*>(wp3 + co * 320 + mh * 160);
        const float* pb  = C3 + mh * 16 * 80 + 2 * j;
#pragma unroll
        for (int mm = 0; mm < 16; mm++) {
            const float* prow = pb + mm * 80;
#pragma unroll
            for (int dy = 0; dy < 5; dy++) {
                float2 ww = __ldg(wq + mm * 5 + dy);
                float2 v0 = *reinterpret_cast<const float2*>(prow + dy * 8);
                float2 v1 = *reinterpret_cast<const float2*>(prow + 40 + dy * 8);
                a0 = fmaf(v0.x, ww.x, fmaf(v0.y, ww.y, a0));
                a1 = fmaf(v1.x, ww.x, fmaf(v1.y, ww.y, a1));
            }
        }
        float* scr = sm + SCR_OFF;
        if (mh) { scr[co * 8 + j] = a0; scr[co * 8 + 4 + j] = a1; }
        __syncthreads();
        if (!mh) {
            const float b = __ldg(bp3 + co);
            sm[F_OFF + co * 8 + j]     = a0 + b + scr[co * 8 + j];
            sm[F_OFF + co * 8 + 4 + j] = a1 + b + scr[co * 8 + 4 + j];
        }
    }
    __syncthreads();

    // ---- heads ----
    {
        const float fv = sm[F_OFF + tid];
        float part[14];
#pragma unroll
        for (int o = 0; o < 7; o++) part[o]     = fv * __ldg(wmu + o * 256 + tid);
#pragma unroll
        for (int o = 0; o < 7; o++) part[7 + o] = fv * __ldg(wlv + o * 256 + tid);
#pragma unroll
        for (int off = 16; off > 0; off >>= 1) {
#pragma unroll
            for (int o = 0; o < 14; o++)
                part[o] += __shfl_down_sync(0xffffffffu, part[o], off);
        }
        float* red = sm + RED_OFF;
        if ((tid & 31) == 0) {
            int wp = tid >> 5;
#pragma unroll
            for (int o = 0; o < 14; o++) red[wp * 14 + o] = part[o];
        }
        __syncthreads();
        if (tid < 14) {
            float s = 0.0f;
#pragma unroll
            for (int wp = 0; wp < 8; wp++) s += red[wp * 14 + tid];
            if (tid < 7) {
                out[(size_t)bi * 7 + tid] = s + __ldg(bmu + tid);
            } else {
                int q = tid - 7;
                float v = s + __ldg(blv + q);
                v = fminf(fmaxf(v, -5.0f), 0.0f);
                out[(size_t)gridDim.x * 7 + (size_t)bi * 7 + q] = v;
            }
        }
    }
}

extern "C" void kernel_launch(void* const* d_in, const int* in_sizes, int n_in,
                              void* d_out, int out_size)
{
    // ---- unit detection: w1 is uniquely 432 elements == 1728 bytes ----
    int div = 1;
    {
        bool saw432 = false, saw1728 = false;
        for (int i = 0; i < n_in; i++) {
            if (in_sizes[i] == 432)  saw432 = true;
            if (in_sizes[i] == 1728) saw1728 = true;
        }
        if (!saw432 && saw1728) div = 4;
    }

    // ---- size-based input dispatch ----
    const float* p[17] = {0};
    int c8 = 0, c16 = 0, c32 = 0, c1792 = 0, c7 = 0;
    long xsz = 0;
    for (int i = 0; i < n_in; i++) {
        const float* q = (const float*)d_in[i];
        const int sz = in_sizes[i] / div;
        switch (sz) {
            case 432:   p[1]  = q; break;                      // w1
            case 1152:  p[3]  = q; break;                      // w2
            case 4608:  p[5]  = q; break;                      // w3
            case 256:   p[7]  = q; break;                      // wp1
            case 2560:  p[9]  = q; break;                      // wp2
            case 10240: p[11] = q; break;                      // wp3
            case 8:    p[c8++   ? 8  : 2]  = q; break;         // b1 then bp1
            case 16:   p[c16++  ? 10 : 4]  = q; break;         // b2 then bp2
            case 32:   p[c32++  ? 12 : 6]  = q; break;         // b3 then bp3
            case 1792: p[c1792++? 15 : 13] = q; break;         // wmu then wlv
            case 7:    p[c7++   ? 16 : 14] = q; break;         // bmu then blv
            default:
                if (sz > xsz) { p[0] = q; xsz = sz; }
                break;
        }
    }
    float* out = (float*)d_out;
    int B = (int)(xsz / (6 * 100 * 32));
    if (B < 1) B = 1;

    enc_kernel<<<B, NT>>>(
        p[0], p[1], p[2], p[3], p[4], p[5], p[6], p[7], p[8], p[9], p[10],
        p[11], p[12], p[13], p[14], p[15], p[16], out);
    (void)out_size;
}